// round 15
// baseline (speedup 1.0000x reference)
#include <cuda_runtime.h>
#include <cuda_fp16.h>
#include <cstdint>

#define NN 100000
#define NE 1600000
#define IND 256
#define HID 128
#define OUTD 64
#define NB ((NN + 1023) / 1024)   // scan blocks

// scratch (allocation-free: __device__ globals)
__device__ int      g_degi[NN];               // in-degree (excl self)
__device__ unsigned g_state[NB];              // lookback scan state
__device__ int      g_off[NN + 1];            // CSR offsets (by destination)
__device__ int      g_cur[NN];                // scatter cursors
__device__ int      g_src[NE];                // CSR source ids
__device__ float    g_dis[NN];
__device__ __half   g_h1[(size_t)NN * HID];   // x @ W1 (unscaled), fp16
__device__ float    g_a1[(size_t)NN * HID];   // relu'ed hidden (fp32)
__device__ __half   g_h2[(size_t)NN * OUTD];  // (a1 @ W2) * dis[row], fp16

// ---------------------------------------------------------------------------
// per-block dtype self-detect helper (int64 node ids < 2^31 -> odd words 0)
// ---------------------------------------------------------------------------
__device__ __forceinline__ int detect_is64(const void* ei) {
    const int* p = (const int*)ei;
    int bad = 0;
#pragma unroll
    for (int k = 0; k < 16; k++)
        bad |= p[2 * ((threadIdx.x & 31) * 16 + k) + 1];
    return !__any_sync(0xffffffff, bad != 0);
}

// degree histogram over col half only
__global__ void k_deg(const void* __restrict__ ei, int e) {
    __shared__ int sh_is64;
    if (threadIdx.x < 32) {
        int is64 = detect_is64(ei);
        if (threadIdx.x == 0) sh_is64 = is64;
    }
    __syncthreads();
    const int is64 = sh_is64;
    const long long* p64 = (const long long*)ei;
    const int* p32 = (const int*)ei;
    for (int i = blockIdx.x * blockDim.x + threadIdx.x; i < e;
         i += gridDim.x * blockDim.x) {
        int c = is64 ? (int)p64[e + i] : p32[e + i];
        c = min(max(c, 0), NN - 1);
        atomicAdd(&g_degi[c], 1);
    }
}

// ---------------------------------------------------------------------------
// single-pass decoupled-lookback scan -> offsets, cursors, dis
// status bits[30:32): 0 = empty, 1 = aggregate, 2 = inclusive prefix
// ---------------------------------------------------------------------------
__global__ __launch_bounds__(1024) void k_scan(int n) {
    __shared__ int wsum[32];
    __shared__ int sh_prev;
    const int b = blockIdx.x;
    const int tid = threadIdx.x;
    const int lane = tid & 31;
    const int wid = tid >> 5;
    const int i = b * 1024 + tid;

    int deg = (i < n) ? g_degi[i] : 0;
    int incl = deg;
#pragma unroll
    for (int d = 1; d < 32; d <<= 1) {
        int t = __shfl_up_sync(0xffffffff, incl, d);
        if (lane >= d) incl += t;
    }
    if (lane == 31) wsum[wid] = incl;
    __syncthreads();
    if (wid == 0) {
        int w = wsum[lane];
#pragma unroll
        for (int d = 1; d < 32; d <<= 1) {
            int t = __shfl_up_sync(0xffffffff, w, d);
            if (lane >= d) w += t;
        }
        wsum[lane] = w;
    }
    __syncthreads();
    incl += (wid > 0) ? wsum[wid - 1] : 0;
    unsigned total = (unsigned)wsum[31];

    if (tid == 0) {
        if (b == 0) {
            atomicExch(&g_state[0], (2u << 30) | total);
            sh_prev = 0;
        } else {
            atomicExch(&g_state[b], (1u << 30) | total);
            unsigned prev = 0;
            for (int j = b - 1; j >= 0; j--) {
                unsigned s;
                do { s = atomicAdd(&g_state[j], 0u); } while ((s >> 30) == 0u);
                prev += s & 0x3fffffffu;
                if ((s >> 30) == 2u) break;
            }
            atomicExch(&g_state[b], (2u << 30) | (prev + total));
            sh_prev = (int)prev;
        }
    }
    __syncthreads();
    incl += sh_prev;

    if (i < n) {
        int start = incl - deg;
        g_off[i] = start;
        g_cur[i] = start;
        g_dis[i] = rsqrtf((float)(deg + 1));  // +1 self-loop
        if (i == n - 1) g_off[n] = incl;
    }
}

// position scatter, reading edge_index directly
__global__ void k_scatter(const void* __restrict__ ei, int e) {
    __shared__ int sh_is64;
    if (threadIdx.x < 32) {
        int is64 = detect_is64(ei);
        if (threadIdx.x == 0) sh_is64 = is64;
    }
    __syncthreads();
    const int is64 = sh_is64;
    const long long* p64 = (const long long*)ei;
    const int* p32 = (const int*)ei;
    for (int i = blockIdx.x * blockDim.x + threadIdx.x; i < e;
         i += gridDim.x * blockDim.x) {
        int r = is64 ? (int)p64[i] : p32[i];
        int c = is64 ? (int)p64[e + i] : p32[e + i];
        r = min(max(r, 0), NN - 1);
        c = min(max(c, 0), NN - 1);
        int pos = atomicAdd(&g_cur[c], 1);
        g_src[pos] = r;
    }
}

// ---------------------------------------------------------------------------
// 3xTF32 GEMM, split hoisted to smem-store time. Inner loop = LDS + MMA only.
// C[M,N] = (A[M,K] @ B[K,N]) * (scale ? scale[row] : 1)
// ---------------------------------------------------------------------------
__device__ __forceinline__ void f32_split(float v, uint32_t& hi, uint32_t& lo) {
    asm("cvt.rna.tf32.f32 %0, %1;" : "=r"(hi) : "f"(v));
    float rem = v - __uint_as_float(hi);
    asm("cvt.rna.tf32.f32 %0, %1;" : "=r"(lo) : "f"(rem));
}

__device__ __forceinline__ void mma_tf32(float* c, const uint32_t* a,
                                         const uint32_t* b) {
    asm volatile(
        "mma.sync.aligned.m16n8k8.row.col.f32.tf32.tf32.f32 "
        "{%0,%1,%2,%3}, {%4,%5,%6,%7}, {%8,%9}, {%0,%1,%2,%3};"
        : "+f"(c[0]), "+f"(c[1]), "+f"(c[2]), "+f"(c[3])
        : "r"(a[0]), "r"(a[1]), "r"(a[2]), "r"(a[3]), "r"(b[0]), "r"(b[1]));
}

template <int K, int N, int BM, int BK, int WM, int WN, typename OutT>
__global__ __launch_bounds__((BM / WM) * (N / WN) * 32) void tf32_gemm(
    const float* __restrict__ A, const float* __restrict__ B,
    OutT* __restrict__ C, const float* __restrict__ scale, int M) {
    constexpr int BN = N;
    constexpr int WARPS_N = BN / WN;
    constexpr int NWARPS = (BM / WM) * WARPS_N;
    constexpr int THREADS = NWARPS * 32;
    constexpr int MT = WM / 16;
    constexpr int NT = WN / 8;
    constexpr int A_LOADS = (BM * BK / 4) / THREADS;
    constexpr int B_LOADS = (BK * BN / 4) / THREADS;
    constexpr int PAD = 8;

    __shared__ float AsH[BK][BM + PAD];
    __shared__ float AsL[BK][BM + PAD];
    __shared__ float BsH[BK][BN + PAD];
    __shared__ float BsL[BK][BN + PAD];

    const int tid = threadIdx.x;
    const int wid = tid >> 5;
    const int lane = tid & 31;
    const int p = lane >> 2;   // 0..7
    const int q = lane & 3;    // 0..3
    const int wm0 = (wid / WARPS_N) * WM;
    const int wn0 = (wid % WARPS_N) * WN;
    const int m0 = blockIdx.x * BM;

    float acc[MT][NT][4] = {};

    float4 aReg[A_LOADS], bReg[B_LOADS];
#pragma unroll
    for (int l = 0; l < A_LOADS; l++) {
        int idx = tid + l * THREADS;
        int r = idx / (BK / 4);
        int kc = (idx % (BK / 4)) * 4;
        int row = m0 + r;
        if (row >= M) row = M - 1;
        aReg[l] = *(const float4*)(A + (size_t)row * K + kc);
    }
#pragma unroll
    for (int l = 0; l < B_LOADS; l++) {
        int flat = (tid + l * THREADS) * 4;
        bReg[l] = *(const float4*)(B + flat);
    }

    for (int k0 = 0; k0 < K; k0 += BK) {
        // commit staged tiles to smem, splitting hi/lo once here
#pragma unroll
        for (int l = 0; l < A_LOADS; l++) {
            int idx = tid + l * THREADS;
            int r = idx / (BK / 4);
            int kc = (idx % (BK / 4)) * 4;
            const float av[4] = {aReg[l].x, aReg[l].y, aReg[l].z, aReg[l].w};
#pragma unroll
            for (int c = 0; c < 4; c++) {
                uint32_t hi, lo;
                f32_split(av[c], hi, lo);
                AsH[kc + c][r] = __uint_as_float(hi);
                AsL[kc + c][r] = __uint_as_float(lo);
            }
        }
#pragma unroll
        for (int l = 0; l < B_LOADS; l++) {
            int flat = (tid + l * THREADS) * 4;
            int k = flat / BN;
            int n = flat % BN;
            const float bv[4] = {bReg[l].x, bReg[l].y, bReg[l].z, bReg[l].w};
#pragma unroll
            for (int c = 0; c < 4; c++) {
                uint32_t hi, lo;
                f32_split(bv[c], hi, lo);
                BsH[k][n + c] = __uint_as_float(hi);
                BsL[k][n + c] = __uint_as_float(lo);
            }
        }
        __syncthreads();

        if (k0 + BK < K) {
#pragma unroll
            for (int l = 0; l < A_LOADS; l++) {
                int idx = tid + l * THREADS;
                int r = idx / (BK / 4);
                int kc = (idx % (BK / 4)) * 4;
                int row = m0 + r;
                if (row >= M) row = M - 1;
                aReg[l] = *(const float4*)(A + (size_t)row * K + k0 + BK + kc);
            }
#pragma unroll
            for (int l = 0; l < B_LOADS; l++) {
                int flat = (tid + l * THREADS) * 4;
                bReg[l] = *(const float4*)(B + (size_t)(k0 + BK) * N + flat);
            }
        }

#pragma unroll
        for (int kk = 0; kk < BK; kk += 8) {
            uint32_t ahi[MT][4], alo[MT][4];
#pragma unroll
            for (int mt = 0; mt < MT; mt++) {
                int r0 = wm0 + mt * 16 + p;
                ahi[mt][0] = __float_as_uint(AsH[kk + q][r0]);
                alo[mt][0] = __float_as_uint(AsL[kk + q][r0]);
                ahi[mt][1] = __float_as_uint(AsH[kk + q][r0 + 8]);
                alo[mt][1] = __float_as_uint(AsL[kk + q][r0 + 8]);
                ahi[mt][2] = __float_as_uint(AsH[kk + q + 4][r0]);
                alo[mt][2] = __float_as_uint(AsL[kk + q + 4][r0]);
                ahi[mt][3] = __float_as_uint(AsH[kk + q + 4][r0 + 8]);
                alo[mt][3] = __float_as_uint(AsL[kk + q + 4][r0 + 8]);
            }
            uint32_t bhi[NT][2], blo[NT][2];
#pragma unroll
            for (int nt = 0; nt < NT; nt++) {
                int c0 = wn0 + nt * 8 + p;
                bhi[nt][0] = __float_as_uint(BsH[kk + q][c0]);
                blo[nt][0] = __float_as_uint(BsL[kk + q][c0]);
                bhi[nt][1] = __float_as_uint(BsH[kk + q + 4][c0]);
                blo[nt][1] = __float_as_uint(BsL[kk + q + 4][c0]);
            }
#pragma unroll
            for (int mt = 0; mt < MT; mt++)
#pragma unroll
                for (int nt = 0; nt < NT; nt++) {
                    mma_tf32(acc[mt][nt], ahi[mt], bhi[nt]);
                    mma_tf32(acc[mt][nt], ahi[mt], blo[nt]);
                    mma_tf32(acc[mt][nt], alo[mt], bhi[nt]);
                }
        }
        __syncthreads();
    }

#pragma unroll
    for (int mt = 0; mt < MT; mt++) {
        int row0 = m0 + wm0 + mt * 16 + p;
        int row1 = row0 + 8;
        float s0 = scale ? ((row0 < M) ? scale[row0] : 0.0f) : 1.0f;
        float s1 = scale ? ((row1 < M) ? scale[row1] : 0.0f) : 1.0f;
#pragma unroll
        for (int nt = 0; nt < NT; nt++) {
            int col = wn0 + nt * 8 + 2 * q;
            if (row0 < M) {
                if constexpr (sizeof(OutT) == 4) {
                    float2 v = make_float2(acc[mt][nt][0] * s0,
                                           acc[mt][nt][1] * s0);
                    *(float2*)((float*)C + (size_t)row0 * N + col) = v;
                } else {
                    __half2 v = __floats2half2_rn(acc[mt][nt][0] * s0,
                                                  acc[mt][nt][1] * s0);
                    *(__half2*)((__half*)C + (size_t)row0 * N + col) = v;
                }
            }
            if (row1 < M) {
                if constexpr (sizeof(OutT) == 4) {
                    float2 v = make_float2(acc[mt][nt][2] * s1,
                                           acc[mt][nt][3] * s1);
                    *(float2*)((float*)C + (size_t)row1 * N + col) = v;
                } else {
                    __half2 v = __floats2half2_rn(acc[mt][nt][2] * s1,
                                                  acc[mt][nt][3] * s1);
                    *(__half2*)((__half*)C + (size_t)row1 * N + col) = v;
                }
            }
        }
    }
}

// ---------------------------------------------------------------------------
// CSR pull aggregation (fp16 gathers via wide loads, fp32 accumulate)
// layer1: a1[n] = relu(dis[n] * (dis[n]*h1[n] + sum dis[s]*h1[s]) + b1)
// ---------------------------------------------------------------------------
__device__ __forceinline__ void acc_row16(float4& acc, const __half* rowp,
                                          int lane, float s) {
    uint2 u = ((const uint2*)rowp)[lane];  // one LDG.64 = 4 halves
    float2 lo = __half22float2(*(const __half2*)&u.x);
    float2 hi = __half22float2(*(const __half2*)&u.y);
    acc.x = fmaf(s, lo.x, acc.x);
    acc.y = fmaf(s, lo.y, acc.y);
    acc.z = fmaf(s, hi.x, acc.z);
    acc.w = fmaf(s, hi.y, acc.w);
}

__global__ __launch_bounds__(256) void k_agg1(const float* __restrict__ b1,
                                              int n) {
    int node = (blockIdx.x * blockDim.x + threadIdx.x) >> 5;
    int lane = threadIdx.x & 31;
    if (node >= n) return;
    int beg = g_off[node];
    int end = g_off[node + 1];
    float dn = g_dis[node];

    float4 acc = {0.f, 0.f, 0.f, 0.f};
    acc_row16(acc, g_h1 + (size_t)node * HID, lane, dn);  // self

    int j = beg;
    for (; j + 32 <= end; j += 32) {
        int s = g_src[j + lane];
        float ds = g_dis[s];
#pragma unroll 8
        for (int k = 0; k < 32; k++) {
            int sk = __shfl_sync(0xffffffff, s, k);
            float dsk = __shfl_sync(0xffffffff, ds, k);
            acc_row16(acc, g_h1 + (size_t)sk * HID, lane, dsk);
        }
    }
    if (j < end) {
        int myi = j + lane;
        int s = (myi < end) ? g_src[myi] : 0;
        float ds = (myi < end) ? g_dis[s] : 0.0f;
        int cnt = end - j;
        for (int k = 0; k < cnt; k++) {
            int sk = __shfl_sync(0xffffffff, s, k);
            float dsk = __shfl_sync(0xffffffff, ds, k);
            acc_row16(acc, g_h1 + (size_t)sk * HID, lane, dsk);
        }
    }

    float4 b = ((const float4*)b1)[lane];
    float4 o;
    o.x = fmaxf(fmaf(acc.x, dn, b.x), 0.0f);
    o.y = fmaxf(fmaf(acc.y, dn, b.y), 0.0f);
    o.z = fmaxf(fmaf(acc.z, dn, b.z), 0.0f);
    o.w = fmaxf(fmaf(acc.w, dn, b.w), 0.0f);
    ((float4*)(g_a1 + (size_t)node * HID))[lane] = o;
}

// layer2 (h2 rows pre-scaled by dis): out[n] = dis[n]*(h2[n]+sum h2[s]) + b2
__global__ __launch_bounds__(256) void k_agg2(const float* __restrict__ b2,
                                              float* __restrict__ out, int n) {
    int node = (blockIdx.x * blockDim.x + threadIdx.x) >> 5;
    int lane = threadIdx.x & 31;
    if (node >= n) return;
    int beg = g_off[node];
    int end = g_off[node + 1];

    float2 acc = __half22float2(
        ((const __half2*)(g_h2 + (size_t)node * OUTD))[lane]);  // self

    int j = beg;
    for (; j + 32 <= end; j += 32) {
        int s = g_src[j + lane];
#pragma unroll 8
        for (int k = 0; k < 32; k++) {
            int sk = __shfl_sync(0xffffffff, s, k);
            float2 v = __half22float2(
                ((const __half2*)(g_h2 + (size_t)sk * OUTD))[lane]);
            acc.x += v.x; acc.y += v.y;
        }
    }
    if (j < end) {
        int myi = j + lane;
        int s = (myi < end) ? g_src[myi] : 0;
        int cnt = end - j;
        for (int k = 0; k < cnt; k++) {
            int sk = __shfl_sync(0xffffffff, s, k);
            float2 v = __half22float2(
                ((const __half2*)(g_h2 + (size_t)sk * OUTD))[lane]);
            acc.x += v.x; acc.y += v.y;
        }
    }

    float sc = g_dis[node];
    float2 b = ((const float2*)b2)[lane];
    float2 o;
    o.x = fmaf(acc.x, sc, b.x);
    o.y = fmaf(acc.y, sc, b.y);
    ((float2*)(out + (size_t)node * OUTD))[lane] = o;
}

// ---------------------------------------------------------------------------
// launch (dual-stream: GEMM1 overlaps the whole CSR build)
// ---------------------------------------------------------------------------
extern "C" void kernel_launch(void* const* d_in, const int* in_sizes, int n_in,
                              void* d_out, int out_size) {
    const float* x = nullptr;
    const void* ei = nullptr;
    const float* W1 = nullptr;
    const float* b1 = nullptr;
    const float* W2 = nullptr;
    const float* b2 = nullptr;
    for (int i = 0; i < n_in; i++) {
        switch (in_sizes[i]) {
            case NN * IND:   x  = (const float*)d_in[i]; break;
            case 2 * NE:     ei = d_in[i];               break;
            case IND * HID:  W1 = (const float*)d_in[i]; break;
            case HID:        b1 = (const float*)d_in[i]; break;
            case HID * OUTD: W2 = (const float*)d_in[i]; break;
            case OUTD:       b2 = (const float*)d_in[i]; break;
            default: break;
        }
    }
    float* out = (float*)d_out;
    const int n = NN;
    const int e = NE;

    __half* h1; cudaGetSymbolAddress((void**)&h1, g_h1);
    float*  a1; cudaGetSymbolAddress((void**)&a1, g_a1);
    __half* h2; cudaGetSymbolAddress((void**)&h2, g_h2);
    float* dis; cudaGetSymbolAddress((void**)&dis, g_dis);
    int*  degi; cudaGetSymbolAddress((void**)&degi, g_degi);
    unsigned* st; cudaGetSymbolAddress((void**)&st, g_state);

    // capture-time fork; stream/event creation happens once per capture call
    cudaStream_t sB;
    cudaEvent_t e0, e1;
    cudaStreamCreateWithFlags(&sB, cudaStreamNonBlocking);
    cudaEventCreateWithFlags(&e0, cudaEventDisableTiming);
    cudaEventCreateWithFlags(&e1, cudaEventDisableTiming);

    // fork: GEMM1 on sB (depends only on inputs)
    cudaEventRecord(e0, 0);
    cudaStreamWaitEvent(sB, e0, 0);
    tf32_gemm<IND, HID, 128, 16, 64, 32, __half>
        <<<(n + 127) / 128, 256, 0, sB>>>(x, W1, h1, nullptr, n);
    cudaEventRecord(e1, sB);

    // default stream: CSR build
    cudaMemsetAsync(degi, 0, NN * sizeof(int));
    cudaMemsetAsync(st, 0, NB * sizeof(unsigned));
    k_deg<<<2048, 256>>>(ei, e);
    k_scan<<<NB, 1024>>>(n);
    k_scatter<<<2048, 256>>>(ei, e);

    // join, then aggregation + layer 2
    cudaStreamWaitEvent(0, e1, 0);
    {
        long long thr = (long long)n * 32;
        k_agg1<<<(int)((thr + 255) / 256), 256>>>(b1, n);
    }
    tf32_gemm<HID, OUTD, 128, 16, 32, 32, __half>
        <<<(n + 127) / 128, 256>>>(a1, W2, h2, dis, n);
    {
        long long thr = (long long)n * 32;
        k_agg2<<<(int)((thr + 255) / 256), 256>>>(b2, out, n);
    }
}

// round 17
// speedup vs baseline: 1.0476x; 1.0476x over previous
#include <cuda_runtime.h>
#include <cuda_fp16.h>
#include <cstdint>

#define NN 100000
#define NE 1600000
#define IND 256
#define HID 128
#define OUTD 64
#define NB ((NN + 1023) / 1024)   // scan blocks

// scratch (allocation-free: __device__ globals)
__device__ int      g_degi[NN];               // in-degree (excl self)
__device__ unsigned g_state[NB];              // lookback scan state
__device__ int      g_off[NN + 1];            // CSR offsets (by destination)
__device__ int      g_cur[NN];                // scatter cursors
__device__ int      g_src[NE];                // CSR source ids
__device__ float    g_dis[NN];
__device__ __half   g_h1[(size_t)NN * HID];   // x @ W1 (unscaled), fp16
__device__ float    g_a1[(size_t)NN * HID];   // relu'ed hidden (fp32)
__device__ __half   g_h2[(size_t)NN * OUTD];  // (a1 @ W2) * dis[row], fp16

// ---------------------------------------------------------------------------
// per-block dtype self-detect helper (int64 node ids < 2^31 -> odd words 0)
// ---------------------------------------------------------------------------
__device__ __forceinline__ int detect_is64(const void* ei) {
    const int* p = (const int*)ei;
    int bad = 0;
#pragma unroll
    for (int k = 0; k < 16; k++)
        bad |= p[2 * ((threadIdx.x & 31) * 16 + k) + 1];
    return !__any_sync(0xffffffff, bad != 0);
}

// degree histogram over col half only
__global__ void k_deg(const void* __restrict__ ei, int e) {
    __shared__ int sh_is64;
    if (threadIdx.x < 32) {
        int is64 = detect_is64(ei);
        if (threadIdx.x == 0) sh_is64 = is64;
    }
    __syncthreads();
    const int is64 = sh_is64;
    const long long* p64 = (const long long*)ei;
    const int* p32 = (const int*)ei;
    for (int i = blockIdx.x * blockDim.x + threadIdx.x; i < e;
         i += gridDim.x * blockDim.x) {
        int c = is64 ? (int)p64[e + i] : p32[e + i];
        c = min(max(c, 0), NN - 1);
        atomicAdd(&g_degi[c], 1);
    }
}

// ---------------------------------------------------------------------------
// single-pass decoupled-lookback scan -> offsets, cursors, dis
// status bits[30:32): 0 = empty, 1 = aggregate, 2 = inclusive prefix
// ---------------------------------------------------------------------------
__global__ __launch_bounds__(1024) void k_scan(int n) {
    __shared__ int wsum[32];
    __shared__ int sh_prev;
    const int b = blockIdx.x;
    const int tid = threadIdx.x;
    const int lane = tid & 31;
    const int wid = tid >> 5;
    const int i = b * 1024 + tid;

    int deg = (i < n) ? g_degi[i] : 0;
    int incl = deg;
#pragma unroll
    for (int d = 1; d < 32; d <<= 1) {
        int t = __shfl_up_sync(0xffffffff, incl, d);
        if (lane >= d) incl += t;
    }
    if (lane == 31) wsum[wid] = incl;
    __syncthreads();
    if (wid == 0) {
        int w = wsum[lane];
#pragma unroll
        for (int d = 1; d < 32; d <<= 1) {
            int t = __shfl_up_sync(0xffffffff, w, d);
            if (lane >= d) w += t;
        }
        wsum[lane] = w;
    }
    __syncthreads();
    incl += (wid > 0) ? wsum[wid - 1] : 0;
    unsigned total = (unsigned)wsum[31];

    if (tid == 0) {
        if (b == 0) {
            atomicExch(&g_state[0], (2u << 30) | total);
            sh_prev = 0;
        } else {
            atomicExch(&g_state[b], (1u << 30) | total);
            unsigned prev = 0;
            for (int j = b - 1; j >= 0; j--) {
                unsigned s;
                do { s = atomicAdd(&g_state[j], 0u); } while ((s >> 30) == 0u);
                prev += s & 0x3fffffffu;
                if ((s >> 30) == 2u) break;
            }
            atomicExch(&g_state[b], (2u << 30) | (prev + total));
            sh_prev = (int)prev;
        }
    }
    __syncthreads();
    incl += sh_prev;

    if (i < n) {
        int start = incl - deg;
        g_off[i] = start;
        g_cur[i] = start;
        g_dis[i] = rsqrtf((float)(deg + 1));  // +1 self-loop
        if (i == n - 1) g_off[n] = incl;
    }
}

// position scatter, reading edge_index directly
__global__ void k_scatter(const void* __restrict__ ei, int e) {
    __shared__ int sh_is64;
    if (threadIdx.x < 32) {
        int is64 = detect_is64(ei);
        if (threadIdx.x == 0) sh_is64 = is64;
    }
    __syncthreads();
    const int is64 = sh_is64;
    const long long* p64 = (const long long*)ei;
    const int* p32 = (const int*)ei;
    for (int i = blockIdx.x * blockDim.x + threadIdx.x; i < e;
         i += gridDim.x * blockDim.x) {
        int r = is64 ? (int)p64[i] : p32[i];
        int c = is64 ? (int)p64[e + i] : p32[e + i];
        r = min(max(r, 0), NN - 1);
        c = min(max(c, 0), NN - 1);
        int pos = atomicAdd(&g_cur[c], 1);
        g_src[pos] = r;
    }
}

// ---------------------------------------------------------------------------
// 2-term fp16-split GEMM on mma.m16n8k16: C = (A@B) * (scale?scale[row]:1)
// A smem m-major, B smem n-major; hi/lo split once at commit.
// Error ~ dropped lo*lo term ~ 2^-22 relative.
// ---------------------------------------------------------------------------
__device__ __forceinline__ void f16_split(float v, __half& hi, __half& lo) {
    hi = __float2half_rn(v);
    lo = __float2half_rn(v - __half2float(hi));
}

__device__ __forceinline__ void mma_f16(float* c, const uint32_t* a,
                                        const uint32_t* b) {
    asm volatile(
        "mma.sync.aligned.m16n8k16.row.col.f32.f16.f16.f32 "
        "{%0,%1,%2,%3}, {%4,%5,%6,%7}, {%8,%9}, {%0,%1,%2,%3};"
        : "+f"(c[0]), "+f"(c[1]), "+f"(c[2]), "+f"(c[3])
        : "r"(a[0]), "r"(a[1]), "r"(a[2]), "r"(a[3]), "r"(b[0]), "r"(b[1]));
}

template <int K, int N, int BM, int BK, int WM, int WN, typename OutT>
__global__ __launch_bounds__((BM / WM) * (N / WN) * 32) void f16s_gemm(
    const float* __restrict__ A, const float* __restrict__ B,
    OutT* __restrict__ C, const float* __restrict__ scale, int M) {
    constexpr int BN = N;
    constexpr int WARPS_N = BN / WN;
    constexpr int NWARPS = (BM / WM) * WARPS_N;
    constexpr int THREADS = NWARPS * 32;
    constexpr int MT = WM / 16;
    constexpr int NT = WN / 8;
    constexpr int A_LOADS = (BM * BK / 4) / THREADS;
    constexpr int B_LOADS = (BK * BN / 4) / THREADS;
    constexpr int PADH = 8;   // halves

    __shared__ __half AsH[BM][BK + PADH];
    __shared__ __half AsL[BM][BK + PADH];
    __shared__ __half BsH[BN][BK + PADH];
    __shared__ __half BsL[BN][BK + PADH];

    const int tid = threadIdx.x;
    const int wid = tid >> 5;
    const int lane = tid & 31;
    const int p = lane >> 2;   // 0..7
    const int q = lane & 3;    // 0..3
    const int wm0 = (wid / WARPS_N) * WM;
    const int wn0 = (wid % WARPS_N) * WN;
    const int m0 = blockIdx.x * BM;

    float acc[MT][NT][4] = {};

    float4 aReg[A_LOADS], bReg[B_LOADS];
#pragma unroll
    for (int l = 0; l < A_LOADS; l++) {
        int idx = tid + l * THREADS;
        int r = idx / (BK / 4);
        int kc = (idx % (BK / 4)) * 4;
        int row = m0 + r;
        if (row >= M) row = M - 1;
        aReg[l] = *(const float4*)(A + (size_t)row * K + kc);
    }
#pragma unroll
    for (int l = 0; l < B_LOADS; l++) {
        int flat = (tid + l * THREADS) * 4;
        bReg[l] = *(const float4*)(B + flat);
    }

    for (int k0 = 0; k0 < K; k0 += BK) {
        // commit staged tiles, splitting hi/lo once
#pragma unroll
        for (int l = 0; l < A_LOADS; l++) {
            int idx = tid + l * THREADS;
            int r = idx / (BK / 4);
            int kc = (idx % (BK / 4)) * 4;
            const float av[4] = {aReg[l].x, aReg[l].y, aReg[l].z, aReg[l].w};
            __half hi[4], lo[4];
#pragma unroll
            for (int c = 0; c < 4; c++) f16_split(av[c], hi[c], lo[c]);
            *(__half2*)&AsH[r][kc]     = __halves2half2(hi[0], hi[1]);
            *(__half2*)&AsH[r][kc + 2] = __halves2half2(hi[2], hi[3]);
            *(__half2*)&AsL[r][kc]     = __halves2half2(lo[0], lo[1]);
            *(__half2*)&AsL[r][kc + 2] = __halves2half2(lo[2], lo[3]);
        }
#pragma unroll
        for (int l = 0; l < B_LOADS; l++) {
            int flat = (tid + l * THREADS) * 4;
            int k = flat / BN;
            int n = flat % BN;
            const float bv[4] = {bReg[l].x, bReg[l].y, bReg[l].z, bReg[l].w};
#pragma unroll
            for (int c = 0; c < 4; c++) {
                __half hi, lo;
                f16_split(bv[c], hi, lo);
                BsH[n + c][k] = hi;   // transpose to n-major
                BsL[n + c][k] = lo;
            }
        }
        __syncthreads();

        if (k0 + BK < K) {
#pragma unroll
            for (int l = 0; l < A_LOADS; l++) {
                int idx = tid + l * THREADS;
                int r = idx / (BK / 4);
                int kc = (idx % (BK / 4)) * 4;
                int row = m0 + r;
                if (row >= M) row = M - 1;
                aReg[l] = *(const float4*)(A + (size_t)row * K + k0 + BK + kc);
            }
#pragma unroll
            for (int l = 0; l < B_LOADS; l++) {
                int flat = (tid + l * THREADS) * 4;
                bReg[l] = *(const float4*)(B + (size_t)(k0 + BK) * N + flat);
            }
        }

#pragma unroll
        for (int kk = 0; kk < BK; kk += 16) {
            uint32_t ah[MT][4], al[MT][4];
#pragma unroll
            for (int mt = 0; mt < MT; mt++) {
                int r0 = wm0 + mt * 16 + p;
                ah[mt][0] = *(const uint32_t*)&AsH[r0][kk + 2 * q];
                ah[mt][1] = *(const uint32_t*)&AsH[r0 + 8][kk + 2 * q];
                ah[mt][2] = *(const uint32_t*)&AsH[r0][kk + 2 * q + 8];
                ah[mt][3] = *(const uint32_t*)&AsH[r0 + 8][kk + 2 * q + 8];
                al[mt][0] = *(const uint32_t*)&AsL[r0][kk + 2 * q];
                al[mt][1] = *(const uint32_t*)&AsL[r0 + 8][kk + 2 * q];
                al[mt][2] = *(const uint32_t*)&AsL[r0][kk + 2 * q + 8];
                al[mt][3] = *(const uint32_t*)&AsL[r0 + 8][kk + 2 * q + 8];
            }
            uint32_t bh[NT][2], bl[NT][2];
#pragma unroll
            for (int nt = 0; nt < NT; nt++) {
                int c0 = wn0 + nt * 8 + p;
                bh[nt][0] = *(const uint32_t*)&BsH[c0][kk + 2 * q];
                bh[nt][1] = *(const uint32_t*)&BsH[c0][kk + 2 * q + 8];
                bl[nt][0] = *(const uint32_t*)&BsL[c0][kk + 2 * q];
                bl[nt][1] = *(const uint32_t*)&BsL[c0][kk + 2 * q + 8];
            }
#pragma unroll
            for (int mt = 0; mt < MT; mt++)
#pragma unroll
                for (int nt = 0; nt < NT; nt++) {
                    mma_f16(acc[mt][nt], ah[mt], bh[nt]);
                    mma_f16(acc[mt][nt], ah[mt], bl[nt]);
                    mma_f16(acc[mt][nt], al[mt], bh[nt]);
                }
        }
        __syncthreads();
    }

#pragma unroll
    for (int mt = 0; mt < MT; mt++) {
        int row0 = m0 + wm0 + mt * 16 + p;
        int row1 = row0 + 8;
        float s0 = scale ? ((row0 < M) ? scale[row0] : 0.0f) : 1.0f;
        float s1 = scale ? ((row1 < M) ? scale[row1] : 0.0f) : 1.0f;
#pragma unroll
        for (int nt = 0; nt < NT; nt++) {
            int col = wn0 + nt * 8 + 2 * q;
            if (row0 < M) {
                if constexpr (sizeof(OutT) == 4) {
                    float2 v = make_float2(acc[mt][nt][0] * s0,
                                           acc[mt][nt][1] * s0);
                    *(float2*)((float*)C + (size_t)row0 * N + col) = v;
                } else {
                    __half2 v = __floats2half2_rn(acc[mt][nt][0] * s0,
                                                  acc[mt][nt][1] * s0);
                    *(__half2*)((__half*)C + (size_t)row0 * N + col) = v;
                }
            }
            if (row1 < M) {
                if constexpr (sizeof(OutT) == 4) {
                    float2 v = make_float2(acc[mt][nt][2] * s1,
                                           acc[mt][nt][3] * s1);
                    *(float2*)((float*)C + (size_t)row1 * N + col) = v;
                } else {
                    __half2 v = __floats2half2_rn(acc[mt][nt][2] * s1,
                                                  acc[mt][nt][3] * s1);
                    *(__half2*)((__half*)C + (size_t)row1 * N + col) = v;
                }
            }
        }
    }
}

// ---------------------------------------------------------------------------
// CSR pull aggregation (fp16 gathers via wide loads, fp32 accumulate)
// layer1: a1[n] = relu(dis[n] * (dis[n]*h1[n] + sum dis[s]*h1[s]) + b1)
// ---------------------------------------------------------------------------
__device__ __forceinline__ void acc_row16(float4& acc, const __half* rowp,
                                          int lane, float s) {
    uint2 u = ((const uint2*)rowp)[lane];  // one LDG.64 = 4 halves
    float2 lo = __half22float2(*(const __half2*)&u.x);
    float2 hi = __half22float2(*(const __half2*)&u.y);
    acc.x = fmaf(s, lo.x, acc.x);
    acc.y = fmaf(s, lo.y, acc.y);
    acc.z = fmaf(s, hi.x, acc.z);
    acc.w = fmaf(s, hi.y, acc.w);
}

__global__ __launch_bounds__(256) void k_agg1(const float* __restrict__ b1,
                                              int n) {
    int node = (blockIdx.x * blockDim.x + threadIdx.x) >> 5;
    int lane = threadIdx.x & 31;
    if (node >= n) return;
    int beg = g_off[node];
    int end = g_off[node + 1];
    float dn = g_dis[node];

    float4 acc = {0.f, 0.f, 0.f, 0.f};
    acc_row16(acc, g_h1 + (size_t)node * HID, lane, dn);  // self

    int j = beg;
    for (; j + 32 <= end; j += 32) {
        int s = g_src[j + lane];
        float ds = g_dis[s];
#pragma unroll 8
        for (int k = 0; k < 32; k++) {
            int sk = __shfl_sync(0xffffffff, s, k);
            float dsk = __shfl_sync(0xffffffff, ds, k);
            acc_row16(acc, g_h1 + (size_t)sk * HID, lane, dsk);
        }
    }
    if (j < end) {
        int myi = j + lane;
        int s = (myi < end) ? g_src[myi] : 0;
        float ds = (myi < end) ? g_dis[s] : 0.0f;
        int cnt = end - j;
        for (int k = 0; k < cnt; k++) {
            int sk = __shfl_sync(0xffffffff, s, k);
            float dsk = __shfl_sync(0xffffffff, ds, k);
            acc_row16(acc, g_h1 + (size_t)sk * HID, lane, dsk);
        }
    }

    float4 b = ((const float4*)b1)[lane];
    float4 o;
    o.x = fmaxf(fmaf(acc.x, dn, b.x), 0.0f);
    o.y = fmaxf(fmaf(acc.y, dn, b.y), 0.0f);
    o.z = fmaxf(fmaf(acc.z, dn, b.z), 0.0f);
    o.w = fmaxf(fmaf(acc.w, dn, b.w), 0.0f);
    ((float4*)(g_a1 + (size_t)node * HID))[lane] = o;
}

// layer2 (h2 rows pre-scaled by dis): out[n] = dis[n]*(h2[n]+sum h2[s]) + b2
__global__ __launch_bounds__(256) void k_agg2(const float* __restrict__ b2,
                                              float* __restrict__ out, int n) {
    int node = (blockIdx.x * blockDim.x + threadIdx.x) >> 5;
    int lane = threadIdx.x & 31;
    if (node >= n) return;
    int beg = g_off[node];
    int end = g_off[node + 1];

    float2 acc = __half22float2(
        ((const __half2*)(g_h2 + (size_t)node * OUTD))[lane]);  // self

    int j = beg;
    for (; j + 32 <= end; j += 32) {
        int s = g_src[j + lane];
#pragma unroll 8
        for (int k = 0; k < 32; k++) {
            int sk = __shfl_sync(0xffffffff, s, k);
            float2 v = __half22float2(
                ((const __half2*)(g_h2 + (size_t)sk * OUTD))[lane]);
            acc.x += v.x; acc.y += v.y;
        }
    }
    if (j < end) {
        int myi = j + lane;
        int s = (myi < end) ? g_src[myi] : 0;
        int cnt = end - j;
        for (int k = 0; k < cnt; k++) {
            int sk = __shfl_sync(0xffffffff, s, k);
            float2 v = __half22float2(
                ((const __half2*)(g_h2 + (size_t)sk * OUTD))[lane]);
            acc.x += v.x; acc.y += v.y;
        }
    }

    float sc = g_dis[node];
    float2 b = ((const float2*)b2)[lane];
    float2 o;
    o.x = fmaf(acc.x, sc, b.x);
    o.y = fmaf(acc.y, sc, b.y);
    ((float2*)(out + (size_t)node * OUTD))[lane] = o;
}

// ---------------------------------------------------------------------------
// launch (dual-stream: GEMM1 overlaps the whole CSR build)
// ---------------------------------------------------------------------------
extern "C" void kernel_launch(void* const* d_in, const int* in_sizes, int n_in,
                              void* d_out, int out_size) {
    const float* x = nullptr;
    const void* ei = nullptr;
    const float* W1 = nullptr;
    const float* b1 = nullptr;
    const float* W2 = nullptr;
    const float* b2 = nullptr;
    for (int i = 0; i < n_in; i++) {
        switch (in_sizes[i]) {
            case NN * IND:   x  = (const float*)d_in[i]; break;
            case 2 * NE:     ei = d_in[i];               break;
            case IND * HID:  W1 = (const float*)d_in[i]; break;
            case HID:        b1 = (const float*)d_in[i]; break;
            case HID * OUTD: W2 = (const float*)d_in[i]; break;
            case OUTD:       b2 = (const float*)d_in[i]; break;
            default: break;
        }
    }
    float* out = (float*)d_out;
    const int n = NN;
    const int e = NE;

    __half* h1; cudaGetSymbolAddress((void**)&h1, g_h1);
    float*  a1; cudaGetSymbolAddress((void**)&a1, g_a1);
    __half* h2; cudaGetSymbolAddress((void**)&h2, g_h2);
    float* dis; cudaGetSymbolAddress((void**)&dis, g_dis);
    int*  degi; cudaGetSymbolAddress((void**)&degi, g_degi);
    unsigned* st; cudaGetSymbolAddress((void**)&st, g_state);

    // capture-time fork; stream/event creation happens once per capture call
    cudaStream_t sB;
    cudaEvent_t e0, e1;
    cudaStreamCreateWithFlags(&sB, cudaStreamNonBlocking);
    cudaEventCreateWithFlags(&e0, cudaEventDisableTiming);
    cudaEventCreateWithFlags(&e1, cudaEventDisableTiming);

    // fork: GEMM1 on sB (depends only on inputs)
    cudaEventRecord(e0, 0);
    cudaStreamWaitEvent(sB, e0, 0);
    f16s_gemm<IND, HID, 128, 32, 64, 32, __half>
        <<<(n + 127) / 128, 256, 0, sB>>>(x, W1, h1, nullptr, n);
    cudaEventRecord(e1, sB);

    // default stream: CSR build
    cudaMemsetAsync(degi, 0, NN * sizeof(int));
    cudaMemsetAsync(st, 0, NB * sizeof(unsigned));
    k_deg<<<2048, 256>>>(ei, e);
    k_scan<<<NB, 1024>>>(n);
    k_scatter<<<2048, 256>>>(ei, e);

    // join, then aggregation + layer 2
    cudaStreamWaitEvent(0, e1, 0);
    {
        long long thr = (long long)n * 32;
        k_agg1<<<(int)((thr + 255) / 256), 256>>>(b1, n);
    }
    f16s_gemm<HID, OUTD, 128, 32, 32, 32, __half>
        <<<(n + 127) / 128, 256>>>(a1, W2, h2, dis, n);
    {
        long long thr = (long long)n * 32;
        k_agg2<<<(int)((thr + 255) / 256), 256>>>(b2, out, n);
    }
}